// round 4
// baseline (speedup 1.0000x reference)
#include <cuda_runtime.h>
#include <math.h>
#include <stdint.h>

#define CS   8
#define TPB  512
#define HID  256
#define ENCL 16
#define DECL 25
#define NV   28

typedef unsigned long long ull;

// precomputed input projections, layout [t][unit 0..255][gate 0..3]
__device__ float g_pre[ENCL * 1024];
__device__ float g_tab[NV * 1024];

// ---------------- smem layout (float offsets) ----------------
#define O_H3B   0               // 3 x 256 h buffers
#define O_CF    768             // cfull [256]
#define O_PRE   1024            // [16][32 units][4 gates] = 2048
#define O_TAB   3072            // [28][32][4] = 3584
#define O_OW    6656            // out_W rows, stride 264 -> 28*264 = 7392
#define O_CATH  14048           // [40]
#define O_CATC  14088           // [40]
#define O_CNEW  14128           // [32]
#define O_WMAX  14160           // 8 x ull (16 floats)
#define O_MBAR  14176           // 3 x ull (6 floats)
#define SMEM_FLOATS 14192
#define SMEM_BYTES  (SMEM_FLOATS * 4)

// ---------------- PTX helpers ----------------
__device__ __forceinline__ uint32_t smem_u32(const void* p) {
    uint32_t a;
    asm("{ .reg .u64 t; cvta.to.shared.u64 t, %1; cvt.u32.u64 %0, t; }" : "=r"(a) : "l"(p));
    return a;
}
__device__ __forceinline__ uint32_t mapa_u32(uint32_t a, uint32_t rank) {
    uint32_t r;
    asm("mapa.shared::cluster.u32 %0, %1, %2;" : "=r"(r) : "r"(a), "r"(rank));
    return r;
}
__device__ __forceinline__ void st_cluster_f32(uint32_t addr, float v) {
    asm volatile("st.shared::cluster.u32 [%0], %1;" :: "r"(addr), "r"(__float_as_uint(v)) : "memory");
}
__device__ __forceinline__ void cluster_bar() {
    asm volatile("barrier.cluster.arrive.aligned;" ::: "memory");
    asm volatile("barrier.cluster.wait.aligned;" ::: "memory");
}
__device__ __forceinline__ void mbar_init(uint32_t a, uint32_t cnt) {
    asm volatile("mbarrier.init.shared.b64 [%0], %1;" :: "r"(a), "r"(cnt) : "memory");
}
__device__ __forceinline__ void mbar_arrive_rel(uint32_t a) {
    asm volatile("mbarrier.arrive.release.cluster.shared::cluster.b64 _, [%0];" :: "r"(a) : "memory");
}
__device__ __forceinline__ void mbar_wait(uint32_t a, uint32_t par) {
    uint32_t done;
    asm volatile("{\n\t.reg .pred p;\n\t"
                 "mbarrier.try_wait.parity.acquire.cluster.shared::cta.b64 p, [%1], %2;\n\t"
                 "selp.b32 %0,1,0,p;\n\t}"
                 : "=r"(done) : "r"(a), "r"(par) : "memory");
    while (!done) {
        asm volatile("{\n\t.reg .pred p;\n\t"
                     "mbarrier.try_wait.parity.acquire.cluster.shared::cta.b64 p, [%1], %2, 0x989680;\n\t"
                     "selp.b32 %0,1,0,p;\n\t}"
                     : "=r"(done) : "r"(a), "r"(par) : "memory");
    }
}
__device__ __forceinline__ void ffma2(ull &acc, ull a, ull b) {
    asm("fma.rn.f32x2 %0, %1, %2, %0;" : "+l"(acc) : "l"(a), "l"(b));
}
__device__ __forceinline__ float ups(ull a) {
    float lo, hi;
    asm("mov.b64 {%0,%1}, %2;" : "=f"(lo), "=f"(hi) : "l"(a));
    return lo + hi;
}
__device__ __forceinline__ float sigf(float x) {
    return __fdividef(1.f, 1.f + __expf(-x));
}
__device__ __forceinline__ float tanhfast(float x) {
    float t = __expf(-2.f * fabsf(x));
    float r = __fdividef(1.f - t, 1.f + t);
    return copysignf(r, x);
}
__device__ __forceinline__ float red32(float s) {
#pragma unroll
    for (int o = 16; o > 0; o >>= 1) s += __shfl_xor_sync(0xffffffffu, s, o);
    return s;
}
__device__ __forceinline__ float dot8(float4 a0, float4 a1, float4 b0, float4 b1) {
    return a0.x*b0.x + a0.y*b0.y + a0.z*b0.z + a0.w*b0.w
         + a1.x*b1.x + a1.y*b1.y + a1.z*b1.z + a1.w*b1.w;
}

// load 2 gate rows (RA, RB) slice s8, rotation-swizzled
__device__ __forceinline__ void load_wrows(const float* W, int RA, int RB, int s8,
                                           ull* wA, ull* wB) {
#pragma unroll
    for (int kk = 0; kk < 8; kk++) {
        int k = (kk + s8) & 7;
        ulonglong2 a = *(const ulonglong2*)(W + RA * HID + s8 * 32 + k * 4);
        ulonglong2 b = *(const ulonglong2*)(W + RB * HID + s8 * 32 + k * 4);
        wA[2*kk] = a.x; wA[2*kk+1] = a.y;
        wB[2*kk] = b.x; wB[2*kk+1] = b.y;
    }
}
// dual packed dot vs smem vec, reduced over 8 s8-lanes (all lanes get sums)
__device__ __forceinline__ void dual_dot(const float* v, int s8,
                                         const ull* wA, const ull* wB,
                                         float &sA, float &sB) {
    ull aA = 0ull, aB = 0ull;
#pragma unroll
    for (int kk = 0; kk < 8; kk++) {
        int k = (kk + s8) & 7;
        ulonglong2 x = *(const ulonglong2*)(v + s8 * 32 + k * 4);
        ffma2(aA, wA[2*kk], x.x); ffma2(aA, wA[2*kk+1], x.y);
        ffma2(aB, wB[2*kk], x.x); ffma2(aB, wB[2*kk+1], x.y);
    }
    float fA = ups(aA), fB = ups(aB);
#pragma unroll
    for (int o = 1; o < 8; o <<= 1) {
        fA += __shfl_xor_sync(0xffffffffu, fA, o);
        fB += __shfl_xor_sync(0xffffffffu, fB, o);
    }
    sA = fA; sB = fB;
}
// single-row packed dot: weights from smem (row stride handled by caller)
__device__ __forceinline__ float one_dot(const float* v, const float* wrow, int s8) {
    ull acc = 0ull;
#pragma unroll
    for (int kk = 0; kk < 8; kk++) {
        int k = (kk + s8) & 7;
        ulonglong2 x = *(const ulonglong2*)(v + s8 * 32 + k * 4);
        ulonglong2 wv = *(const ulonglong2*)(wrow + s8 * 32 + k * 4);
        ffma2(acc, wv.x, x.x); ffma2(acc, wv.y, x.y);
    }
    float f = ups(acc);
#pragma unroll
    for (int o = 1; o < 8; o <<= 1) f += __shfl_xor_sync(0xffffffffu, f, o);
    return f;
}

// ================= kernel 1: projection tables (wide) =================
__global__ void __launch_bounds__(256) table_kernel(
    const int* data,
    const float* enc_Wih, const float* enc_bih, const float* enc_bhh, const float* enc_emb,
    const float* dec_Wih, const float* dec_bih, const float* dec_bhh, const float* dec_emb)
{
    const int tid  = threadIdx.x;
    const int w    = tid >> 5;
    const int lane = tid & 31;
    const int g    = blockIdx.x;
    const int m    = w >> 2;
    const int R    = g * 4 + (w & 3);          // gate row 0..1023
    const int u    = R & 255, gi = R >> 8;     // unit, gate

    if (m == 0) {
        const float4* p = (const float4*)(enc_Wih + R * HID);
        float4 a0 = p[lane * 2], a1 = p[lane * 2 + 1];
        float bias = enc_bih[R] + enc_bhh[R];
#pragma unroll
        for (int t = 0; t < ENCL; t++) {
            const float4* x = (const float4*)(enc_emb + data[t] * HID);
            float4 x0 = x[lane * 2], x1 = x[lane * 2 + 1];
            float s = red32(dot8(a0, a1, x0, x1));
            if (lane == 0) g_pre[t * 1024 + u * 4 + gi] = s + bias;
        }
    } else {
        const float4* p = (const float4*)(dec_Wih + R * HID);
        float4 a0 = p[lane * 2], a1 = p[lane * 2 + 1];
        float bias = dec_bih[R] + dec_bhh[R];
#pragma unroll
        for (int tk = 0; tk < NV; tk++) {
            const float4* x = (const float4*)(dec_emb + tk * HID);
            float4 x0 = x[lane * 2], x1 = x[lane * 2 + 1];
            x0.x = fmaxf(x0.x, 0.f); x0.y = fmaxf(x0.y, 0.f);
            x0.z = fmaxf(x0.z, 0.f); x0.w = fmaxf(x0.w, 0.f);
            x1.x = fmaxf(x1.x, 0.f); x1.y = fmaxf(x1.y, 0.f);
            x1.z = fmaxf(x1.z, 0.f); x1.w = fmaxf(x1.w, 0.f);
            float s = red32(dot8(a0, a1, x0, x1));
            if (lane == 0) g_tab[tk * 1024 + u * 4 + gi] = s + bias;
        }
    }
}

// ================= kernel 2: sequential LSTM, mbarrier dataflow =================
__global__ void __launch_bounds__(TPB, 1) __cluster_dims__(CS, 1, 1) vae_kernel(
    const int* data_c, const int* target_c, const float* cond_emb,
    const float* enc_Whh,
    const float* hmu_W, const float* hmu_b, const float* cmu_W, const float* cmu_b,
    const float* fc1_W, const float* fc1_b, const float* fc2_W, const float* fc2_b,
    const float* dec_Whh,
    const float* out_W, const float* out_b,
    float* out, int out_size)
{
    extern __shared__ __align__(16) float sm[];
    float* h3b    = sm + O_H3B;
    float* cfull  = sm + O_CF;
    float* pre_sh = sm + O_PRE;
    float* tab_sh = sm + O_TAB;
    float* ow_sh  = sm + O_OW;
    float* cat_h  = sm + O_CATH;
    float* cat_c  = sm + O_CATC;
    float* cnew_sh= sm + O_CNEW;
    volatile ull* wmax_sh = (volatile ull*)(sm + O_WMAX);

    const int tid  = threadIdx.x;
    const int w    = tid >> 5;
    const int lane = tid & 31;
    const int s8   = lane & 7;
    const int q    = lane >> 3;          // gate index for this lane's rows
    const int b    = blockIdx.x;
    const int L    = lane;               // updater lane if L<2
    const int ug   = b * 32 + 2 * w + (L & 1);   // global unit for lanes 0/1

    const uint32_t hb  = smem_u32(h3b);
    const uint32_t cfb = smem_u32(cfull);
    const uint32_t mbb = smem_u32((const void*)(sm + O_MBAR));

    // gate rows this warp computes: gate q of units 2w, 2w+1
    const int RA = q * HID + b * 32 + 2 * w;
    const int RB = RA + 1;

    // recurrent weights -> regs (encoder first)
    ull wA[16], wB[16];
    load_wrows(enc_Whh, RA, RB, s8, wA, wB);

    // mbarriers
    if (tid == 0) {
#pragma unroll
        for (int i = 0; i < 3; i++) mbar_init(mbb + i * 8, 8);
    }
    // arrive address for warp0 lanes<8
    uint32_t amap = 0;
    if (w == 0 && lane < 8) amap = mapa_u32(mbb, (uint32_t)lane);

    // ---- prologue smem fills ----
    for (int i = tid; i < NV * 64; i += TPB) {          // out_W, stride-264 rows
        int row = i >> 6, c4 = i & 63;
        ((float4*)(ow_sh + row * 264))[c4] = ((const float4*)out_W)[i];
    }
    for (int i = tid; i < ENCL * 32; i += TPB)          // pre slice [t][32u][4g]
        ((float4*)pre_sh)[i] = ((const float4*)g_pre)[(i >> 5) * 256 + b * 32 + (i & 31)];
    for (int i = tid; i < NV * 32; i += TPB)            // tab slice
        ((float4*)tab_sh)[i] = ((const float4*)g_tab)[(i >> 5) * 256 + b * 32 + (i & 31)];

    // logits row + bias for warps 0..6
    const int lrow = w * 4 + q;                         // 0..27 valid for w<7
    float obv = (w < 7) ? out_b[lrow] : 0.f;

    // ---- h0 (replicated) and c0 (lanes 0/1 per warp) ----
    const int dcid = data_c[0], tcid = target_c[0];
    if (tid < HID) {
        float v = (tid >= HID - 8) ? cond_emb[dcid * 8 + (tid - (HID - 8))] : 0.f;
        h3b[tid] = v;                                   // buffer 0
    }
    float creg = 0.f;
    if (L < 2) creg = (ug >= HID - 8) ? cond_emb[dcid * 8 + (ug - (HID - 8))] : 0.f;

    __syncthreads();
    cluster_bar();                                      // mbars visible cluster-wide

    int ph0 = 0, ph1 = 0, ph2 = 0;

    // ================= encoder =================
#pragma unroll 1
    for (int n = 0; n < ENCL; n++) {
        int cb = n % 3, nb = (n + 1) % 3;
        if (n > 0) {
            if (cb == 0)      { mbar_wait(mbb + 0, ph0 & 1); if (tid == 0) {} ph0++; }
            else if (cb == 1) { mbar_wait(mbb + 8, ph1 & 1); ph1++; }
            else              { mbar_wait(mbb + 16, ph2 & 1); ph2++; }
        }
        float sA, sB;
        dual_dot(h3b + cb * HID, s8, wA, wB, sA, sB);
        // gather the 4 gates into lanes 0/1
        float a0 = __shfl_sync(0xffffffffu, sA, 0),  a1 = __shfl_sync(0xffffffffu, sA, 8);
        float a2 = __shfl_sync(0xffffffffu, sA, 16), a3 = __shfl_sync(0xffffffffu, sA, 24);
        float b0 = __shfl_sync(0xffffffffu, sB, 0),  b1 = __shfl_sync(0xffffffffu, sB, 8);
        float b2 = __shfl_sync(0xffffffffu, sB, 16), b3 = __shfl_sync(0xffffffffu, sB, 24);
        if (L < 2) {
            float4 pr = *(const float4*)(pre_sh + n * 128 + (2 * w + L) * 4);
            float gi = (L ? b0 : a0) + pr.x;
            float gf = (L ? b1 : a1) + pr.y;
            float gg = (L ? b2 : a2) + pr.z;
            float go = (L ? b3 : a3) + pr.w;
            float c = sigf(gf) * creg + sigf(gi) * tanhfast(gg);
            float h = sigf(go) * tanhfast(c);
            creg = c;
            uint32_t off = (uint32_t)((nb * HID + ug) * 4);
#pragma unroll
            for (int r = 0; r < CS; r++) st_cluster_f32(mapa_u32(hb, r) + off, h);
            if (n == ENCL - 1) {
                uint32_t co = (uint32_t)(ug * 4);
#pragma unroll
                for (int r = 0; r < CS; r++) st_cluster_f32(mapa_u32(cfb, r) + co, c);
            }
        }
        __syncthreads();
        if (n < ENCL - 1) {
            if (w == 0 && lane < 8) mbar_arrive_rel(amap + nb * 8);
        }
    }
    cluster_bar();   // hT (buffer 1) + cfull visible everywhere

    // ================= latent heads + decoder init =================
    {
        const float4* hv = (const float4*)(h3b + HID) + lane * 2;
        float4 h0v = hv[0], h1v = hv[1];
        const float4* cv = (const float4*)cfull + lane * 2;
        float4 c0v = cv[0], c1v = cv[1];
#pragma unroll
        for (int half = 0; half < 2; half++) {
            int rr = w + half * 16;
            const float4* pp = (const float4*)(hmu_W + rr * HID);
            float4 a0 = pp[lane * 2], a1 = pp[lane * 2 + 1];
            float s = red32(dot8(a0, a1, h0v, h1v));
            if (lane == 0) cat_h[rr] = s + hmu_b[rr];
            pp = (const float4*)(cmu_W + rr * HID);
            a0 = pp[lane * 2]; a1 = pp[lane * 2 + 1];
            s = red32(dot8(a0, a1, c0v, c1v));
            if (lane == 0) cat_c[rr] = s + cmu_b[rr];
        }
    }
    if (tid < 8) {
        float v = cond_emb[tcid * 8 + tid];
        cat_h[32 + tid] = v; cat_c[32 + tid] = v;
    }
    __syncthreads();
    float newv = 0.f;
    if (tid < HID) {
        float s = fc1_b[tid];
        const float* wr = fc1_W + tid * 40;
#pragma unroll
        for (int k = 0; k < 40; k++) s += cat_h[k] * wr[k];
        newv = s;
    }
    if (tid < 32) {
        int j = b * 32 + tid;
        float s = fc2_b[j];
        const float* wr = fc2_W + j * 40;
#pragma unroll
        for (int k = 0; k < 40; k++) s += cat_c[k] * wr[k];
        cnew_sh[tid] = s;
    }
    __syncthreads();
    if (tid < HID) h3b[tid] = newv;                     // dh -> buffer 0
    if (L < 2) creg = cnew_sh[2 * w + (L & 1)];

    // decoder recurrent weights
    load_wrows(dec_Whh, RA, RB, s8, wA, wB);
    __syncthreads();
    cluster_bar();                                      // protect buffer1/cfull reads

    // ================= decoder =================
#pragma unroll 1
    for (int m = 0; m < DECL; m++) {
        int cb = m % 3, nb = (m + 1) % 3;
        if (m > 0) {
            if (cb == 0)      { mbar_wait(mbb + 0, ph0 & 1); ph0++; }
            else if (cb == 1) { mbar_wait(mbb + 8, ph1 & 1); ph1++; }
            else              { mbar_wait(mbb + 16, ph2 & 1); ph2++; }
        }
        const float* hcur = h3b + cb * HID;
        float lg = 0.f;
        if (w < 7 && m > 0) {                            // logits of prev step
            lg = one_dot(hcur, ow_sh + lrow * 264, s8) + obv;
            uint32_t bits = __float_as_uint(lg);
            uint32_t key = (bits & 0x80000000u) ? ~bits : (bits | 0x80000000u);
            ull cmp = ((ull)key << 8) | (ull)(255 - lrow);
#pragma unroll
            for (int o = 8; o <= 16; o <<= 1) {
                ull ot = __shfl_xor_sync(0xffffffffu, cmp, o);
                if (ot > cmp) cmp = ot;
            }
            if (lane == 0) wmax_sh[w] = cmp;
        }
        float sA, sB;
        dual_dot(hcur, s8, wA, wB, sA, sB);
        __syncthreads();                                 // wmax + gates ready
        int tok = 0;
        if (m > 0) {
            ull v = (lane < 7) ? wmax_sh[lane] : 0ull;
#pragma unroll
            for (int o = 1; o < 32; o <<= 1) {
                ull ot = __shfl_xor_sync(0xffffffffu, v, o);
                if (ot > v) v = ot;
            }
            tok = 255 - (int)(v & 0xffu);
        }
        float a0 = __shfl_sync(0xffffffffu, sA, 0),  a1 = __shfl_sync(0xffffffffu, sA, 8);
        float a2 = __shfl_sync(0xffffffffu, sA, 16), a3 = __shfl_sync(0xffffffffu, sA, 24);
        float b0 = __shfl_sync(0xffffffffu, sB, 0),  b1 = __shfl_sync(0xffffffffu, sB, 8);
        float b2 = __shfl_sync(0xffffffffu, sB, 16), b3 = __shfl_sync(0xffffffffu, sB, 24);
        if (L < 2) {
            float4 pr = *(const float4*)(tab_sh + tok * 128 + (2 * w + L) * 4);
            float gi = (L ? b0 : a0) + pr.x;
            float gf = (L ? b1 : a1) + pr.y;
            float gg = (L ? b2 : a2) + pr.z;
            float go = (L ? b3 : a3) + pr.w;
            float c = sigf(gf) * creg + sigf(gi) * tanhfast(gg);
            float h = sigf(go) * tanhfast(c);
            creg = c;
            uint32_t off = (uint32_t)((nb * HID + ug) * 4);
#pragma unroll
            for (int r = 0; r < CS; r++) st_cluster_f32(mapa_u32(hb, r) + off, h);
        }
        __syncthreads();
        if (w == 0 && lane < 8) mbar_arrive_rel(amap + nb * 8);
        if (b == 0 && m > 0) {
            if (w < 7 && s8 == 0) out[(m - 1) * NV + lrow] = lg;
            if (w == 7 && lane == 0) out[NV * DECL + (m - 1)] = (float)tok;
        }
    }

    // ---- tail: logits/argmax of final step (h in buffer 25%3 = 1) ----
    {
        mbar_wait(mbb + 8, ph1 & 1); ph1++;
        const float* hcur = h3b + HID;
        float lg = 0.f;
        if (w < 7) {
            lg = one_dot(hcur, ow_sh + lrow * 264, s8) + obv;
            uint32_t bits = __float_as_uint(lg);
            uint32_t key = (bits & 0x80000000u) ? ~bits : (bits | 0x80000000u);
            ull cmp = ((ull)key << 8) | (ull)(255 - lrow);
#pragma unroll
            for (int o = 8; o <= 16; o <<= 1) {
                ull ot = __shfl_xor_sync(0xffffffffu, cmp, o);
                if (ot > cmp) cmp = ot;
            }
            if (lane == 0) wmax_sh[w] = cmp;
        }
        __syncthreads();
        if (b == 0) {
            if (w < 7 && s8 == 0) out[(DECL - 1) * NV + lrow] = lg;
            if (w == 7 && lane == 0) {
                ull v = wmax_sh[0];
#pragma unroll
                for (int i = 1; i < 7; i++) { ull ot = wmax_sh[i]; if (ot > v) v = ot; }
                out[NV * DECL + (DECL - 1)] = (float)(255 - (int)(v & 0xffu));
            }
        }
    }
    cluster_bar();
    (void)out_size;
}

extern "C" void kernel_launch(void* const* d_in, const int* in_sizes, int n_in,
                              void* d_out, int out_size) {
    (void)in_sizes; (void)n_in;
    const int*   data     = (const int*)  d_in[0];
    const int*   data_c   = (const int*)  d_in[1];
    const int*   target_c = (const int*)  d_in[2];
    const float* cond_emb = (const float*)d_in[3];
    const float* enc_emb  = (const float*)d_in[4];
    const float* enc_Wih  = (const float*)d_in[5];
    const float* enc_Whh  = (const float*)d_in[6];
    const float* enc_bih  = (const float*)d_in[7];
    const float* enc_bhh  = (const float*)d_in[8];
    const float* hmu_W    = (const float*)d_in[9];
    const float* hmu_b    = (const float*)d_in[10];
    const float* cmu_W    = (const float*)d_in[11];
    const float* cmu_b    = (const float*)d_in[12];
    const float* fc1_W    = (const float*)d_in[13];
    const float* fc1_b    = (const float*)d_in[14];
    const float* fc2_W    = (const float*)d_in[15];
    const float* fc2_b    = (const float*)d_in[16];
    const float* dec_emb  = (const float*)d_in[17];
    const float* dec_Wih  = (const float*)d_in[18];
    const float* dec_Whh  = (const float*)d_in[19];
    const float* dec_bih  = (const float*)d_in[20];
    const float* dec_bhh  = (const float*)d_in[21];
    const float* out_W    = (const float*)d_in[22];
    const float* out_b    = (const float*)d_in[23];

    table_kernel<<<256, 256>>>(data, enc_Wih, enc_bih, enc_bhh, enc_emb,
                               dec_Wih, dec_bih, dec_bhh, dec_emb);

    cudaFuncSetAttribute(vae_kernel, cudaFuncAttributeMaxDynamicSharedMemorySize, SMEM_BYTES);
    vae_kernel<<<CS, TPB, SMEM_BYTES>>>(data_c, target_c, cond_emb,
                                        enc_Whh,
                                        hmu_W, hmu_b, cmu_W, cmu_b,
                                        fc1_W, fc1_b, fc2_W, fc2_b,
                                        dec_Whh,
                                        out_W, out_b,
                                        (float*)d_out, out_size);
}

// round 5
// speedup vs baseline: 1.0316x; 1.0316x over previous
#include <cuda_runtime.h>
#include <math.h>
#include <stdint.h>

#define CS   8
#define TPB  512
#define HID  256
#define ENCL 16
#define DECL 25
#define NV   28

typedef unsigned long long ull;

// precomputed input projections, layout [t][unit 0..255][gate 0..3]
__device__ float g_pre[ENCL * 1024];
__device__ float g_tab[NV * 1024];

// ---------------- smem layout (float offsets) ----------------
#define O_H3B   0               // 3 x 256 h buffers
#define O_CF    768             // cfull [256]
#define O_PRE   1024            // [16][32 units][4 gates] = 2048
#define O_TAB   3072            // [28][32][4] = 3584
#define O_OW    6656            // out_W rows, stride 264 -> 28*264 = 7392
#define O_CATH  14048           // [40]
#define O_CATC  14088           // [40]
#define O_CNEW  14128           // [32]
#define O_WMAX  14160           // 8 x ull (16 floats)
#define O_TAGS  14176           // 24 ints (3 slots x 8 ranks)
#define SMEM_FLOATS 14200
#define SMEM_BYTES  (SMEM_FLOATS * 4)

// ---------------- PTX helpers ----------------
__device__ __forceinline__ uint32_t smem_u32(const void* p) {
    uint32_t a;
    asm("{ .reg .u64 t; cvta.to.shared.u64 t, %1; cvt.u32.u64 %0, t; }" : "=r"(a) : "l"(p));
    return a;
}
__device__ __forceinline__ uint32_t mapa_u32(uint32_t a, uint32_t rank) {
    uint32_t r;
    asm("mapa.shared::cluster.u32 %0, %1, %2;" : "=r"(r) : "r"(a), "r"(rank));
    return r;
}
__device__ __forceinline__ void st_cluster_f32(uint32_t addr, float v) {
    asm volatile("st.shared::cluster.u32 [%0], %1;" :: "r"(addr), "r"(__float_as_uint(v)) : "memory");
}
__device__ __forceinline__ void st_rel_cluster_u32(uint32_t addr, uint32_t v) {
    asm volatile("st.release.cluster.shared::cluster.u32 [%0], %1;" :: "r"(addr), "r"(v) : "memory");
}
__device__ __forceinline__ int ld_vol_s32(uint32_t addr) {
    int v;
    asm volatile("ld.volatile.shared.s32 %0, [%1];" : "=r"(v) : "r"(addr) : "memory");
    return v;
}
__device__ __forceinline__ void cluster_bar() {
    asm volatile("barrier.cluster.arrive.aligned;" ::: "memory");
    asm volatile("barrier.cluster.wait.aligned;" ::: "memory");
}
// all lanes spin until tag[slot][s8] >= n for every rank (each lane watches rank s8)
__device__ __forceinline__ void wait_tags(uint32_t tagsb, int slot, int s8, int n) {
    uint32_t a = tagsb + (uint32_t)((slot * 8 + s8) * 4);
    while (!__all_sync(0xffffffffu, ld_vol_s32(a) >= n)) { }
}
__device__ __forceinline__ void ffma2(ull &acc, ull a, ull b) {
    asm("fma.rn.f32x2 %0, %1, %2, %0;" : "+l"(acc) : "l"(a), "l"(b));
}
__device__ __forceinline__ float ups(ull a) {
    float lo, hi;
    asm("mov.b64 {%0,%1}, %2;" : "=f"(lo), "=f"(hi) : "l"(a));
    return lo + hi;
}
__device__ __forceinline__ float sigf(float x) {
    return __fdividef(1.f, 1.f + __expf(-x));
}
__device__ __forceinline__ float tanhfast(float x) {
    float t = __expf(-2.f * fabsf(x));
    float r = __fdividef(1.f - t, 1.f + t);
    return copysignf(r, x);
}
__device__ __forceinline__ float red32(float s) {
#pragma unroll
    for (int o = 16; o > 0; o >>= 1) s += __shfl_xor_sync(0xffffffffu, s, o);
    return s;
}
__device__ __forceinline__ float dot8(float4 a0, float4 a1, float4 b0, float4 b1) {
    return a0.x*b0.x + a0.y*b0.y + a0.z*b0.z + a0.w*b0.w
         + a1.x*b1.x + a1.y*b1.y + a1.z*b1.z + a1.w*b1.w;
}

// load 2 gate rows (RA, RB) slice s8, rotation-swizzled
__device__ __forceinline__ void load_wrows(const float* W, int RA, int RB, int s8,
                                           ull* wA, ull* wB) {
#pragma unroll
    for (int kk = 0; kk < 8; kk++) {
        int k = (kk + s8) & 7;
        ulonglong2 a = *(const ulonglong2*)(W + RA * HID + s8 * 32 + k * 4);
        ulonglong2 b = *(const ulonglong2*)(W + RB * HID + s8 * 32 + k * 4);
        wA[2*kk] = a.x; wA[2*kk+1] = a.y;
        wB[2*kk] = b.x; wB[2*kk+1] = b.y;
    }
}
// dual packed dot vs smem vec, reduced over 8 s8-lanes (all lanes get sums)
__device__ __forceinline__ void dual_dot(const float* v, int s8,
                                         const ull* wA, const ull* wB,
                                         float &sA, float &sB) {
    ull aA = 0ull, aB = 0ull;
#pragma unroll
    for (int kk = 0; kk < 8; kk++) {
        int k = (kk + s8) & 7;
        ulonglong2 x = *(const ulonglong2*)(v + s8 * 32 + k * 4);
        ffma2(aA, wA[2*kk], x.x); ffma2(aA, wA[2*kk+1], x.y);
        ffma2(aB, wB[2*kk], x.x); ffma2(aB, wB[2*kk+1], x.y);
    }
    float fA = ups(aA), fB = ups(aB);
#pragma unroll
    for (int o = 1; o < 8; o <<= 1) {
        fA += __shfl_xor_sync(0xffffffffu, fA, o);
        fB += __shfl_xor_sync(0xffffffffu, fB, o);
    }
    sA = fA; sB = fB;
}
// single-row (per q-group) packed dot vs smem vec, reduced over 8 s8-lanes
__device__ __forceinline__ float one_dot(const float* v, const float* wrow, int s8) {
    ull acc = 0ull;
#pragma unroll
    for (int kk = 0; kk < 8; kk++) {
        int k = (kk + s8) & 7;
        ulonglong2 x = *(const ulonglong2*)(v + s8 * 32 + k * 4);
        ulonglong2 wv = *(const ulonglong2*)(wrow + s8 * 32 + k * 4);
        ffma2(acc, wv.x, x.x); ffma2(acc, wv.y, x.y);
    }
    float f = ups(acc);
#pragma unroll
    for (int o = 1; o < 8; o <<= 1) f += __shfl_xor_sync(0xffffffffu, f, o);
    return f;
}

// ================= kernel 1: projection tables (wide) =================
__global__ void __launch_bounds__(256) table_kernel(
    const int* data,
    const float* enc_Wih, const float* enc_bih, const float* enc_bhh, const float* enc_emb,
    const float* dec_Wih, const float* dec_bih, const float* dec_bhh, const float* dec_emb)
{
    const int tid  = threadIdx.x;
    const int w    = tid >> 5;
    const int lane = tid & 31;
    const int g    = blockIdx.x;
    const int m    = w >> 2;
    const int R    = g * 4 + (w & 3);          // gate row 0..1023
    const int u    = R & 255, gi = R >> 8;     // unit, gate

    if (m == 0) {
        const float4* p = (const float4*)(enc_Wih + R * HID);
        float4 a0 = p[lane * 2], a1 = p[lane * 2 + 1];
        float bias = enc_bih[R] + enc_bhh[R];
#pragma unroll
        for (int t = 0; t < ENCL; t++) {
            const float4* x = (const float4*)(enc_emb + data[t] * HID);
            float4 x0 = x[lane * 2], x1 = x[lane * 2 + 1];
            float s = red32(dot8(a0, a1, x0, x1));
            if (lane == 0) g_pre[t * 1024 + u * 4 + gi] = s + bias;
        }
    } else {
        const float4* p = (const float4*)(dec_Wih + R * HID);
        float4 a0 = p[lane * 2], a1 = p[lane * 2 + 1];
        float bias = dec_bih[R] + dec_bhh[R];
#pragma unroll
        for (int tk = 0; tk < NV; tk++) {
            const float4* x = (const float4*)(dec_emb + tk * HID);
            float4 x0 = x[lane * 2], x1 = x[lane * 2 + 1];
            x0.x = fmaxf(x0.x, 0.f); x0.y = fmaxf(x0.y, 0.f);
            x0.z = fmaxf(x0.z, 0.f); x0.w = fmaxf(x0.w, 0.f);
            x1.x = fmaxf(x1.x, 0.f); x1.y = fmaxf(x1.y, 0.f);
            x1.z = fmaxf(x1.z, 0.f); x1.w = fmaxf(x1.w, 0.f);
            float s = red32(dot8(a0, a1, x0, x1));
            if (lane == 0) g_tab[tk * 1024 + u * 4 + gi] = s + bias;
        }
    }
}

// ================= kernel 2: sequential LSTM, tag-spin dataflow =================
__global__ void __launch_bounds__(TPB, 1) __cluster_dims__(CS, 1, 1) vae_kernel(
    const int* data_c, const int* target_c, const float* cond_emb,
    const float* enc_Whh,
    const float* hmu_W, const float* hmu_b, const float* cmu_W, const float* cmu_b,
    const float* fc1_W, const float* fc1_b, const float* fc2_W, const float* fc2_b,
    const float* dec_Whh,
    const float* out_W, const float* out_b,
    float* out, int out_size)
{
    extern __shared__ __align__(16) float sm[];
    float* h3b    = sm + O_H3B;
    float* cfull  = sm + O_CF;
    float* pre_sh = sm + O_PRE;
    float* tab_sh = sm + O_TAB;
    float* ow_sh  = sm + O_OW;
    float* cat_h  = sm + O_CATH;
    float* cat_c  = sm + O_CATC;
    float* cnew_sh= sm + O_CNEW;
    volatile ull* wmax_sh = (volatile ull*)(sm + O_WMAX);
    int*   tags   = (int*)(sm + O_TAGS);

    const int tid  = threadIdx.x;
    const int w    = tid >> 5;
    const int lane = tid & 31;
    const int s8   = lane & 7;
    const int q    = lane >> 3;
    const int b    = blockIdx.x;
    const int L    = lane;                        // updater lane if L<2
    const int ug   = b * 32 + 2 * w + (L & 1);    // global unit for lanes 0/1

    const uint32_t hb    = smem_u32(h3b);
    const uint32_t cfb   = smem_u32(cfull);
    const uint32_t tagsb = smem_u32(tags);

    // gate rows this warp computes: gate q of units 2w, 2w+1
    const int RA = q * HID + b * 32 + 2 * w;
    const int RB = RA + 1;

    // recurrent weights -> regs (encoder first)
    ull wA[16], wB[16];
    load_wrows(enc_Whh, RA, RB, s8, wA, wB);

    // remote addresses (hoisted)
    uint32_t hmap[CS];
#pragma unroll
    for (int r = 0; r < CS; r++) hmap[r] = mapa_u32(hb, r);
    uint32_t tagmap = 0;
    if (w == 0 && lane < 8) tagmap = mapa_u32(tagsb, (uint32_t)lane);

    // ---- prologue smem fills ----
    for (int i = tid; i < NV * 64; i += TPB) {          // out_W, stride-264 rows
        int row = i >> 6, c4 = i & 63;
        ((float4*)(ow_sh + row * 264))[c4] = ((const float4*)out_W)[i];
    }
    for (int i = tid; i < ENCL * 32; i += TPB)          // pre slice [t][32u][4g]
        ((float4*)pre_sh)[i] = ((const float4*)g_pre)[(i >> 5) * 256 + b * 32 + (i & 31)];
    for (int i = tid; i < NV * 32; i += TPB)            // tab slice
        ((float4*)tab_sh)[i] = ((const float4*)g_tab)[(i >> 5) * 256 + b * 32 + (i & 31)];

    // logits row + bias for warps 0..6
    const int lrow = w * 4 + q;                         // 0..27 valid for w<7
    float obv = (w < 7) ? out_b[lrow] : 0.f;

    // ---- h0 (replicated, slot 0) and c0 (lanes 0/1 per warp) ----
    const int dcid = data_c[0], tcid = target_c[0];
    if (tid < HID) {
        float v = (tid >= HID - 8) ? cond_emb[dcid * 8 + (tid - (HID - 8))] : 0.f;
        h3b[tid] = v;
    }
    float creg = 0.f;
    if (L < 2) creg = (ug >= HID - 8) ? cond_emb[dcid * 8 + (ug - (HID - 8))] : 0.f;

    // tags: slot0 ready (h_0 is local), others invalid
    if (tid < 24) tags[tid] = (tid < 8) ? 0 : -1;

    __syncthreads();
    cluster_bar();                                      // tag init visible before any remote flag

    // ================= encoder: N = 0..15 =================
#pragma unroll 1
    for (int n = 0; n < ENCL; n++) {
        int slot = n % 3, slot2 = (n + 1) % 3;
        wait_tags(tagsb, slot, s8, n);
        float sA, sB;
        dual_dot(h3b + slot * HID, s8, wA, wB, sA, sB);
        float a0 = __shfl_sync(0xffffffffu, sA, 0),  a1 = __shfl_sync(0xffffffffu, sA, 8);
        float a2 = __shfl_sync(0xffffffffu, sA, 16), a3 = __shfl_sync(0xffffffffu, sA, 24);
        float b0 = __shfl_sync(0xffffffffu, sB, 0),  b1 = __shfl_sync(0xffffffffu, sB, 8);
        float b2 = __shfl_sync(0xffffffffu, sB, 16), b3 = __shfl_sync(0xffffffffu, sB, 24);
        if (L < 2) {
            float4 pr = *(const float4*)(pre_sh + n * 128 + (2 * w + L) * 4);
            float gi = (L ? b0 : a0) + pr.x;
            float gf = (L ? b1 : a1) + pr.y;
            float gg = (L ? b2 : a2) + pr.z;
            float go = (L ? b3 : a3) + pr.w;
            float c = sigf(gf) * creg + sigf(gi) * tanhfast(gg);
            float h = sigf(go) * tanhfast(c);
            creg = c;
            uint32_t off = (uint32_t)((slot2 * HID + ug) * 4);
#pragma unroll
            for (int r = 0; r < CS; r++) st_cluster_f32(hmap[r] + off, h);
            if (n == ENCL - 1) {
                uint32_t co = (uint32_t)(ug * 4);
#pragma unroll
                for (int r = 0; r < CS; r++) st_cluster_f32(mapa_u32(cfb, r) + co, c);
            }
        }
        __syncthreads();
        if (w == 0 && lane < 8)
            st_rel_cluster_u32(tagmap + (uint32_t)((slot2 * 8 + b) * 4), (uint32_t)(n + 1));
    }

    // hT tagged 16, slot 1; wait for all chunks (covers cfull too)
    wait_tags(tagsb, 1, s8, ENCL);

    // ================= latent heads + decoder init (redundant per CTA) =================
    {
        const float4* hv = (const float4*)(h3b + HID) + lane * 2;
        float4 h0v = hv[0], h1v = hv[1];
        const float4* cv = (const float4*)cfull + lane * 2;
        float4 c0v = cv[0], c1v = cv[1];
#pragma unroll
        for (int half = 0; half < 2; half++) {
            int rr = w + half * 16;
            const float4* pp = (const float4*)(hmu_W + rr * HID);
            float4 a0 = pp[lane * 2], a1 = pp[lane * 2 + 1];
            float s = red32(dot8(a0, a1, h0v, h1v));
            if (lane == 0) cat_h[rr] = s + hmu_b[rr];
            pp = (const float4*)(cmu_W + rr * HID);
            a0 = pp[lane * 2]; a1 = pp[lane * 2 + 1];
            s = red32(dot8(a0, a1, c0v, c1v));
            if (lane == 0) cat_c[rr] = s + cmu_b[rr];
        }
    }
    if (tid < 8) {
        float v = cond_emb[tcid * 8 + tid];
        cat_h[32 + tid] = v; cat_c[32 + tid] = v;
    }
    __syncthreads();
    float newv = 0.f;
    if (tid < HID) {
        float s = fc1_b[tid];
        const float* wr = fc1_W + tid * 40;
#pragma unroll
        for (int k = 0; k < 40; k++) s += cat_h[k] * wr[k];
        newv = s;
    }
    if (tid < 32) {
        int j = b * 32 + tid;
        float s = fc2_b[j];
        const float* wr = fc2_W + j * 40;
#pragma unroll
        for (int k = 0; k < 40; k++) s += cat_c[k] * wr[k];
        cnew_sh[tid] = s;
    }
    __syncthreads();
    if (tid < HID) h3b[2 * HID + tid] = newv;           // dh -> slot 2 (N=17)
    if (tid < 8) tags[2 * 8 + tid] = 17;                // local-only production
    if (L < 2) creg = cnew_sh[2 * w + (L & 1)];

    // decoder recurrent weights
    load_wrows(dec_Whh, RA, RB, s8, wA, wB);
    __syncthreads();

    // ================= decoder: N = 17..41 =================
#pragma unroll 1
    for (int m = 0; m < DECL; m++) {
        int N = 17 + m;
        int slot = N % 3, slot2 = (N + 1) % 3;
        wait_tags(tagsb, slot, s8, N);
        const float* hcur = h3b + slot * HID;
        float lg = 0.f;
        if (m > 0 && w < 7) {                            // logits of ref iter m-1
            lg = one_dot(hcur, ow_sh + lrow * 264, s8) + obv;
            uint32_t bits = __float_as_uint(lg);
            uint32_t key = (bits & 0x80000000u) ? ~bits : (bits | 0x80000000u);
            ull cmp = ((ull)key << 8) | (ull)(255 - lrow);
#pragma unroll
            for (int o = 8; o <= 16; o <<= 1) {
                ull ot = __shfl_xor_sync(0xffffffffu, cmp, o);
                if (ot > cmp) cmp = ot;
            }
            if (lane == 0) wmax_sh[w] = cmp;
        }
        float sA, sB;
        dual_dot(hcur, s8, wA, wB, sA, sB);
        __syncthreads();                                 // wmax visible
        if (b == 0 && m > 0 && w < 7 && s8 == 0)
            out[(m - 1) * NV + lrow] = lg;
        float a0 = __shfl_sync(0xffffffffu, sA, 0),  a1 = __shfl_sync(0xffffffffu, sA, 8);
        float a2 = __shfl_sync(0xffffffffu, sA, 16), a3 = __shfl_sync(0xffffffffu, sA, 24);
        float b0 = __shfl_sync(0xffffffffu, sB, 0),  b1 = __shfl_sync(0xffffffffu, sB, 8);
        float b2 = __shfl_sync(0xffffffffu, sB, 16), b3 = __shfl_sync(0xffffffffu, sB, 24);
        if (L < 2) {
            int tok = 0;
            if (m > 0) {
                ull v = wmax_sh[0];
#pragma unroll
                for (int i = 1; i < 7; i++) { ull ot = wmax_sh[i]; if (ot > v) v = ot; }
                tok = 255 - (int)(v & 0xffu);
                if (b == 0 && w == 7 && L == 0) out[NV * DECL + (m - 1)] = (float)tok;
            }
            float4 pr = *(const float4*)(tab_sh + tok * 128 + (2 * w + L) * 4);
            float gi = (L ? b0 : a0) + pr.x;
            float gf = (L ? b1 : a1) + pr.y;
            float gg = (L ? b2 : a2) + pr.z;
            float go = (L ? b3 : a3) + pr.w;
            float c = sigf(gf) * creg + sigf(gi) * tanhfast(gg);
            float h = sigf(go) * tanhfast(c);
            creg = c;
            uint32_t off = (uint32_t)((slot2 * HID + ug) * 4);
#pragma unroll
            for (int r = 0; r < CS; r++) st_cluster_f32(hmap[r] + off, h);
        }
        __syncthreads();
        if (w == 0 && lane < 8)
            st_rel_cluster_u32(tagmap + (uint32_t)((slot2 * 8 + b) * 4), (uint32_t)(N + 1));
    }

    // ---- tail: logits/argmax of final step (h tagged 42, slot 0) ----
    if (b == 0) {
        wait_tags(tagsb, 0, s8, 42);
        const float* hcur = h3b;
        float lg = 0.f;
        if (w < 7) {
            lg = one_dot(hcur, ow_sh + lrow * 264, s8) + obv;
            uint32_t bits = __float_as_uint(lg);
            uint32_t key = (bits & 0x80000000u) ? ~bits : (bits | 0x80000000u);
            ull cmp = ((ull)key << 8) | (ull)(255 - lrow);
#pragma unroll
            for (int o = 8; o <= 16; o <<= 1) {
                ull ot = __shfl_xor_sync(0xffffffffu, cmp, o);
                if (ot > cmp) cmp = ot;
            }
            if (lane == 0) wmax_sh[w] = cmp;
        }
        __syncthreads();
        if (w < 7 && s8 == 0) out[(DECL - 1) * NV + lrow] = lg;
        if (w == 7 && lane == 0) {
            ull v = wmax_sh[0];
#pragma unroll
            for (int i = 1; i < 7; i++) { ull ot = wmax_sh[i]; if (ot > v) v = ot; }
            out[NV * DECL + (DECL - 1)] = (float)(255 - (int)(v & 0xffu));
        }
    }
    cluster_bar();
    (void)out_size;
}

extern "C" void kernel_launch(void* const* d_in, const int* in_sizes, int n_in,
                              void* d_out, int out_size) {
    (void)in_sizes; (void)n_in;
    const int*   data     = (const int*)  d_in[0];
    const int*   data_c   = (const int*)  d_in[1];
    const int*   target_c = (const int*)  d_in[2];
    const float* cond_emb = (const float*)d_in[3];
    const float* enc_emb  = (const float*)d_in[4];
    const float* enc_Wih  = (const float*)d_in[5];
    const float* enc_Whh  = (const float*)d_in[6];
    const float* enc_bih  = (const float*)d_in[7];
    const float* enc_bhh  = (const float*)d_in[8];
    const float* hmu_W    = (const float*)d_in[9];
    const float* hmu_b    = (const float*)d_in[10];
    const float* cmu_W    = (const float*)d_in[11];
    const float* cmu_b    = (const float*)d_in[12];
    const float* fc1_W    = (const float*)d_in[13];
    const float* fc1_b    = (const float*)d_in[14];
    const float* fc2_W    = (const float*)d_in[15];
    const float* fc2_b    = (const float*)d_in[16];
    const float* dec_emb  = (const float*)d_in[17];
    const float* dec_Wih  = (const float*)d_in[18];
    const float* dec_Whh  = (const float*)d_in[19];
    const float* dec_bih  = (const float*)d_in[20];
    const float* dec_bhh  = (const float*)d_in[21];
    const float* out_W    = (const float*)d_in[22];
    const float* out_b    = (const float*)d_in[23];

    table_kernel<<<256, 256>>>(data, enc_Wih, enc_bih, enc_bhh, enc_emb,
                               dec_Wih, dec_bih, dec_bhh, dec_emb);

    cudaFuncSetAttribute(vae_kernel, cudaFuncAttributeMaxDynamicSharedMemorySize, SMEM_BYTES);
    vae_kernel<<<CS, TPB, SMEM_BYTES>>>(data_c, target_c, cond_emb,
                                        enc_Whh,
                                        hmu_W, hmu_b, cmu_W, cmu_b,
                                        fc1_W, fc1_b, fc2_W, fc2_b,
                                        dec_Whh,
                                        out_W, out_b,
                                        (float*)d_out, out_size);
}